// round 10
// baseline (speedup 1.0000x reference)
#include <cuda_runtime.h>
#include <cstdint>

#define N_NODES 100000
#define N_EDGES 1600000
#define D 128
#define EF 32

// scratch (no allocations allowed): x = h + agg, CSR structures
__device__ float g_x[(size_t)N_NODES * D];        // 51.2 MB
__device__ int   g_cnt[N_NODES];
__device__ int   g_rowptr[N_NODES + 1];
__device__ int   g_cursor[N_NODES];
__device__ int2  g_csr[N_EDGES];                  // (src, edge_id) bucketed by dst

typedef unsigned long long u64;

__device__ __forceinline__ u64 pack2(float lo, float hi) {
    u64 r; asm("mov.b64 %0, {%1, %2};" : "=l"(r) : "f"(lo), "f"(hi)); return r;
}
__device__ __forceinline__ void unpack2(u64 v, float &lo, float &hi) {
    asm("mov.b64 {%0, %1}, %2;" : "=f"(lo), "=f"(hi) : "l"(v));
}
__device__ __forceinline__ u64 ffma2(u64 a, u64 b, u64 c) {
    u64 d; asm("fma.rn.f32x2 %0, %1, %2, %3;" : "=l"(d) : "l"(a), "l"(b), "l"(c));
    return d;
}

// ---------------------------------------------------------------------------
// CSR build: zero counts -> histogram -> scan -> bucket scatter
// ---------------------------------------------------------------------------
__global__ void k_zero() {
    int i = blockIdx.x * blockDim.x + threadIdx.x;
    if (i < N_NODES) g_cnt[i] = 0;
}

__global__ void k_hist(const int2* __restrict__ eidx) {
    int i = blockIdx.x * blockDim.x + threadIdx.x;   // exactly N_EDGES threads
    atomicAdd(&g_cnt[eidx[i].y], 1);                 // compiles to RED (no return)
}

// single-block exclusive scan of g_cnt -> g_rowptr / g_cursor
#define SCAN_CHUNK 98
__global__ void k_scan() {
    __shared__ int ssum[1024];
    int t = threadIdx.x;
    int base = t * SCAN_CHUNK;
    int s = 0;
    for (int j = 0; j < SCAN_CHUNK; j++) {
        int idx = base + j;
        if (idx < N_NODES) s += g_cnt[idx];
    }
    ssum[t] = s;
    __syncthreads();
    for (int off = 1; off < 1024; off <<= 1) {
        int v = 0;
        if (t >= off) v = ssum[t - off];
        __syncthreads();
        ssum[t] += v;
        __syncthreads();
    }
    int run = (t == 0) ? 0 : ssum[t - 1];
    for (int j = 0; j < SCAN_CHUNK; j++) {
        int idx = base + j;
        if (idx < N_NODES) {
            g_rowptr[idx] = run;
            g_cursor[idx] = run;
            run += g_cnt[idx];
        }
    }
    if (t == 1023) g_rowptr[N_NODES] = ssum[1023];
}

__global__ void k_scatter(const int2* __restrict__ eidx) {
    int i = blockIdx.x * blockDim.x + threadIdx.x;   // exactly N_EDGES threads
    int2 e = eidx[i];
    int pos = atomicAdd(&g_cursor[e.y], 1);
    g_csr[pos] = make_int2(e.x, i);
}

// ---------------------------------------------------------------------------
// Aggregation (one warp per dst, no atomics):
//   x[dst] = h[dst] + Sum h[src] + (Sum edge_attr) @ W_e + deg * b_e
// Lane-parallel CSR prefetch: one coalesced LDG.64 fetches 32 (src,eid)
// pairs; shfl broadcasts (26 cyc) replace uniform L2 round-trips (234 cyc);
// gathers issue in predicated batches of 8 (MLP ~= degree, no serial tail).
// ---------------------------------------------------------------------------
__global__ void __launch_bounds__(256) k_agg(
    const float4* __restrict__ h4, const float* __restrict__ ea,
    const float* __restrict__ We, const float* __restrict__ be)
{
    __shared__ __align__(16) float4 sWe[EF * 32];    // 16 KB
    __shared__ float4 sbe[32];

    int tid = threadIdx.x;
    for (int i = tid; i < EF * 32; i += 256) sWe[i] = ((const float4*)We)[i];
    if (tid < 32) sbe[tid] = ((const float4*)be)[tid];
    __syncthreads();

    int w = tid >> 5, lane = tid & 31;
    int dst = blockIdx.x * 8 + w;                    // grid covers exactly N_NODES
    int start = g_rowptr[dst];
    int end   = g_rowptr[dst + 1];

    float4 acc = h4[(size_t)dst * 32 + lane];        // includes self term
    float accA = 0.f;

    for (int j0 = start; j0 < end; j0 += 32) {
        int idx = j0 + lane;
        int2 c = (idx < end) ? g_csr[idx] : make_int2(0, 0);
        int m = end - j0;                            // warp-uniform
        if (m > 32) m = 32;

        for (int jj = 0; jj < m; jj += 8) {
            int   s[8], eid[8];
            bool  ok[8];
            #pragma unroll
            for (int u = 0; u < 8; u++) {
                ok[u] = (jj + u) < m;
                int lsel = ok[u] ? (jj + u) : 0;
                s[u]   = __shfl_sync(0xffffffffu, c.x, lsel);
                eid[u] = __shfl_sync(0xffffffffu, c.y, lsel);
            }
            float4 v[8]; float a[8];
            #pragma unroll
            for (int u = 0; u < 8; u++) {
                if (ok[u]) {
                    v[u] = h4[(size_t)s[u] * 32 + lane];
                    a[u] = ea[(size_t)eid[u] * EF + lane];
                } else {
                    v[u] = make_float4(0.f, 0.f, 0.f, 0.f);
                    a[u] = 0.f;
                }
            }
            #pragma unroll
            for (int u = 0; u < 8; u++) {
                acc.x += v[u].x; acc.y += v[u].y;
                acc.z += v[u].z; acc.w += v[u].w;
                accA  += a[u];
            }
        }
    }

    // tiny per-node GEMM: accA (32-vec, distributed lane k) @ W_e[:, lane cols]
    #pragma unroll
    for (int k = 0; k < EF; k++) {
        float a = __shfl_sync(0xffffffffu, accA, k);
        float4 wv = sWe[k * 32 + lane];
        acc.x += a * wv.x; acc.y += a * wv.y;
        acc.z += a * wv.z; acc.w += a * wv.w;
    }
    float fd = (float)(end - start);
    float4 bv = sbe[lane];
    acc.x += fd * bv.x; acc.y += fd * bv.y;
    acc.z += fd * bv.z; acc.w += fd * bv.w;

    ((float4*)g_x)[(size_t)dst * 32 + lane] = acc;
}

// ---------------------------------------------------------------------------
// MLP: out = gelu_exact(x @ W1 + b1) @ W2 + b2   (at packed-FFMA2 roofline)
// ---------------------------------------------------------------------------
__global__ void __launch_bounds__(256) k_mlp(
    const float* __restrict__ W1, const float* __restrict__ b1,
    const float* __restrict__ W2, const float* __restrict__ b2,
    float* __restrict__ out)
{
    extern __shared__ u64 xsd[];               // [64][128] u64 = 64 KB
    int tid = threadIdx.x;
    int lane = tid & 31, w = tid >> 5;
    int row0 = blockIdx.x * 64;

    for (int f = tid; f < 64 * 32; f += 256) {
        int r = f >> 5, c4 = f & 31;
        float4 v = make_float4(0.f, 0.f, 0.f, 0.f);
        if (row0 + r < N_NODES)
            v = ((const float4*)g_x)[(size_t)(row0 + r) * 32 + c4];
        u64* p = xsd + r * 128 + c4 * 4;
        p[0] = pack2(v.x, v.x); p[1] = pack2(v.y, v.y);
        p[2] = pack2(v.z, v.z); p[3] = pack2(v.w, v.w);
    }
    __syncthreads();

    u64 acc[8][2];
    {
        float4 bv = *(const float4*)(b1 + lane * 4);
        #pragma unroll
        for (int i = 0; i < 8; i++) {
            acc[i][0] = pack2(bv.x, bv.y);
            acc[i][1] = pack2(bv.z, bv.w);
        }
    }
    #pragma unroll 4
    for (int k = 0; k < D; k++) {
        ulonglong2 wv = *(const ulonglong2*)(W1 + (size_t)k * D + lane * 4);
        #pragma unroll
        for (int i = 0; i < 8; i++) {
            u64 xv = xsd[(w * 8 + i) * 128 + k];
            acc[i][0] = ffma2(xv, wv.x, acc[i][0]);
            acc[i][1] = ffma2(xv, wv.y, acc[i][1]);
        }
    }
    __syncthreads();

    #pragma unroll
    for (int i = 0; i < 8; i++) {
        float t0, t1, t2, t3;
        unpack2(acc[i][0], t0, t1);
        unpack2(acc[i][1], t2, t3);
        t0 *= normcdff(t0); t1 *= normcdff(t1);
        t2 *= normcdff(t2); t3 *= normcdff(t3);
        u64* p = xsd + (w * 8 + i) * 128 + lane * 4;
        p[0] = pack2(t0, t0); p[1] = pack2(t1, t1);
        p[2] = pack2(t2, t2); p[3] = pack2(t3, t3);
    }
    __syncthreads();

    {
        float4 bv = *(const float4*)(b2 + lane * 4);
        #pragma unroll
        for (int i = 0; i < 8; i++) {
            acc[i][0] = pack2(bv.x, bv.y);
            acc[i][1] = pack2(bv.z, bv.w);
        }
    }
    #pragma unroll 4
    for (int k = 0; k < D; k++) {
        ulonglong2 wv = *(const ulonglong2*)(W2 + (size_t)k * D + lane * 4);
        #pragma unroll
        for (int i = 0; i < 8; i++) {
            u64 xv = xsd[(w * 8 + i) * 128 + k];
            acc[i][0] = ffma2(xv, wv.x, acc[i][0]);
            acc[i][1] = ffma2(xv, wv.y, acc[i][1]);
        }
    }

    #pragma unroll
    for (int i = 0; i < 8; i++) {
        int r = row0 + w * 8 + i;
        if (r < N_NODES) {
            float o0, o1, o2, o3;
            unpack2(acc[i][0], o0, o1);
            unpack2(acc[i][1], o2, o3);
            *(float4*)(out + (size_t)r * D + lane * 4) = make_float4(o0, o1, o2, o3);
        }
    }
}

// ---------------------------------------------------------------------------
extern "C" void kernel_launch(void* const* d_in, const int* in_sizes, int n_in,
                              void* d_out, int out_size) {
    const float* h  = (const float*)d_in[0];
    const int2* ei  = (const int2*)d_in[1];
    const float* ea = (const float*)d_in[2];
    const float* We = (const float*)d_in[3];
    const float* be = (const float*)d_in[4];
    const float* W1 = (const float*)d_in[5];
    const float* b1 = (const float*)d_in[6];
    const float* W2 = (const float*)d_in[7];
    const float* b2 = (const float*)d_in[8];
    float* out = (float*)d_out;

    cudaFuncSetAttribute(k_mlp, cudaFuncAttributeMaxDynamicSharedMemorySize, 65536);

    k_zero<<<(N_NODES + 1023) / 1024, 1024>>>();
    k_hist<<<N_EDGES / 256, 256>>>(ei);
    k_scan<<<1, 1024>>>();
    k_scatter<<<N_EDGES / 256, 256>>>(ei);
    k_agg<<<N_NODES / 8, 256>>>((const float4*)h, ea, We, be);
    k_mlp<<<(N_NODES + 63) / 64, 256, 65536>>>(W1, b1, W2, b2, out);
}